// round 11
// baseline (speedup 1.0000x reference)
#include <cuda_runtime.h>
#include <math.h>

#define NMAXN 100000
#define EMAXE 1600000

// ---------------- scratch (static __device__ — no allocations) ------------
__device__ int   g_is64;                          // edge dtype flag
__device__ int   g_cnt[NMAXN];                    // in-degree (excl self-loop)
__device__ int   g_off[NMAXN];                    // CSR offsets (by dst)
__device__ int   g_cur[NMAXN];                    // fill cursors
__device__ int2  g_edge[EMAXE];                   // {src,dst} int32
__device__ int   g_srcs[EMAXE];                   // CSR src lists
__device__ float g_y [(size_t)NMAXN * 64];        // (x@W1)*dinv[row]
__device__ float g_z [(size_t)NMAXN * 64];        // relu(layer1 out)
__device__ float g_y2[(size_t)NMAXN * 16];        // (z@W2)*dinv[row]

// ---------------- K0: zero counts + dtype probe ---------------------------
// int64 indices (<2^31) have zero high words at every odd 32-bit slot.
__global__ void __launch_bounds__(256) k_prep(const int* __restrict__ ei32, int n) {
    int i = blockIdx.x * blockDim.x + threadIdx.x;
    if (i < n) g_cnt[i] = 0;
    if (i == 0) {
        int any = 0;
        #pragma unroll 8
        for (int k = 0; k < 256; k++) any |= ei32[2 * k + 1];
        g_is64 = (any == 0) ? 1 : 0;
    }
}

// ---------------- K1: edges -> int2, count in-degrees ---------------------
__global__ void __launch_bounds__(256) k_edges(const void* __restrict__ eiv, int e) {
    int t = blockIdx.x * blockDim.x + threadIdx.x;
    if (t >= e) return;
    int s, d;
    if (g_is64) {
        const long long* ei = (const long long*)eiv;
        s = (int)ei[t];
        d = (int)ei[t + e];
    } else {
        const int* ei = (const int*)eiv;
        s = ei[t];
        d = ei[t + e];
    }
    g_edge[t] = make_int2(s, d);
    atomicAdd(&g_cnt[d], 1);
}

// ---------------- K2: exclusive scan of counts (single block) -------------
__global__ void __launch_bounds__(1024) k_scan(int n) {
    __shared__ int sums[1024];
    int tid = threadIdx.x;
    int chunk = (n + 1023) >> 10;
    int lo = tid * chunk, hi = min(n, lo + chunk);
    int s = 0;
    for (int i = lo; i < hi; i++) s += g_cnt[i];
    sums[tid] = s;
    __syncthreads();
    for (int d = 1; d < 1024; d <<= 1) {
        int t2 = (tid >= d) ? sums[tid - d] : 0;
        __syncthreads();
        sums[tid] += t2;
        __syncthreads();
    }
    int base = sums[tid] - s;   // exclusive prefix
    for (int i = lo; i < hi; i++) {
        g_off[i] = base;
        g_cur[i] = base;
        base += g_cnt[i];
    }
}

// ---------------- K3: y = (x @ W1) * dinv[row] ----------------------------
__global__ void __launch_bounds__(256) k_gemm1(const float* __restrict__ x,
                                               const float* __restrict__ W1, int n) {
    __shared__ float xs[64 * 68];
    __shared__ float ws[64 * 64];
    int tid = threadIdx.x;
    int r0 = blockIdx.x * 64;
    int rows = min(64, n - r0);

    const float4* W4 = (const float4*)W1;
    float4* ws4 = (float4*)ws;
    #pragma unroll 4
    for (int i = tid; i < 1024; i += 256) ws4[i] = W4[i];

    const float4* x4 = (const float4*)(x + (size_t)r0 * 64);
    for (int i = tid; i < rows * 16; i += 256) {
        int r = i >> 4, q = i & 15;
        ((float4*)(xs + r * 68))[q] = x4[i];
    }
    __syncthreads();

    int r = tid >> 2;
    int g = (tid & 3) * 16;
    int row = r0 + r;
    if (row < n) {
        float4 a0 = make_float4(0,0,0,0), a1 = a0, a2 = a0, a3 = a0;
        #pragma unroll
        for (int k = 0; k < 64; k++) {
            float xv = xs[r * 68 + k];
            const float4* wr = (const float4*)(ws + k * 64 + g);
            float4 w0 = wr[0], w1 = wr[1], w2 = wr[2], w3 = wr[3];
            a0.x += xv * w0.x; a0.y += xv * w0.y; a0.z += xv * w0.z; a0.w += xv * w0.w;
            a1.x += xv * w1.x; a1.y += xv * w1.y; a1.z += xv * w1.z; a1.w += xv * w1.w;
            a2.x += xv * w2.x; a2.y += xv * w2.y; a2.z += xv * w2.z; a2.w += xv * w2.w;
            a3.x += xv * w3.x; a3.y += xv * w3.y; a3.z += xv * w3.z; a3.w += xv * w3.w;
        }
        float di = rsqrtf((float)g_cnt[row] + 1.0f);
        float4* yo = (float4*)(g_y + (size_t)row * 64 + g);
        a0.x *= di; a0.y *= di; a0.z *= di; a0.w *= di;
        a1.x *= di; a1.y *= di; a1.z *= di; a1.w *= di;
        a2.x *= di; a2.y *= di; a2.z *= di; a2.w *= di;
        a3.x *= di; a3.y *= di; a3.z *= di; a3.w *= di;
        yo[0] = a0; yo[1] = a1; yo[2] = a2; yo[3] = a3;
    }
}

// ---------------- K4: CSR bucket fill -------------------------------------
__global__ void __launch_bounds__(256) k_fill(int e) {
    int t = blockIdx.x * blockDim.x + threadIdx.x;
    if (t >= e) return;
    int2 p = g_edge[t];
    int pos = atomicAdd(&g_cur[p.y], 1);
    g_srcs[pos] = p.x;
}

// ---------------- K5: gather64 + relu epilogue ----------------------------
// 16 lanes per node; register accumulation; z = relu(di*(acc+y)+b1)
__global__ void __launch_bounds__(256) k_gather64(const float* __restrict__ b1, int n) {
    int t = blockIdx.x * blockDim.x + threadIdx.x;
    int node = t >> 4;
    if (node >= n) return;
    int c = t & 15;
    int off = g_off[node];
    int cnt = g_cnt[node];
    int end = off + cnt;
    const float4* y4 = (const float4*)g_y;
    float4 acc = make_float4(0.f, 0.f, 0.f, 0.f);
    int i = off;
    for (; i + 2 <= end; i += 2) {
        int s0 = g_srcs[i], s1 = g_srcs[i + 1];
        float4 v0 = y4[(size_t)s0 * 16 + c];
        float4 v1 = y4[(size_t)s1 * 16 + c];
        acc.x += v0.x + v1.x; acc.y += v0.y + v1.y;
        acc.z += v0.z + v1.z; acc.w += v0.w + v1.w;
    }
    if (i < end) {
        float4 v0 = y4[(size_t)g_srcs[i] * 16 + c];
        acc.x += v0.x; acc.y += v0.y; acc.z += v0.z; acc.w += v0.w;
    }
    float di = rsqrtf((float)cnt + 1.0f);
    float4 yv = y4[(size_t)node * 16 + c];
    float4 bv = __ldg(&((const float4*)b1)[c]);
    float4 z;
    z.x = fmaxf(di * (acc.x + yv.x) + bv.x, 0.f);
    z.y = fmaxf(di * (acc.y + yv.y) + bv.y, 0.f);
    z.z = fmaxf(di * (acc.z + yv.z) + bv.z, 0.f);
    z.w = fmaxf(di * (acc.w + yv.w) + bv.w, 0.f);
    ((float4*)g_z)[(size_t)node * 16 + c] = z;
}

// ---------------- K6: y2 = (z @ W2) * dinv[row] ---------------------------
__global__ void __launch_bounds__(256) k_layer2(const float* __restrict__ W2, int n) {
    __shared__ float w2s[64 * 16];
    __shared__ float zs[16 * 65];
    int tid = threadIdx.x;
    #pragma unroll 4
    for (int i = tid; i < 1024; i += 256) w2s[i] = W2[i];

    int r = tid >> 4;
    int tc = tid & 15;
    int row = blockIdx.x * 16 + r;
    bool ok = row < n;
    if (ok) {
        #pragma unroll
        for (int j = 0; j < 4; j++) {
            int c = tc + j * 16;
            zs[r * 65 + c] = g_z[(size_t)row * 64 + c];
        }
    }
    __syncthreads();
    if (ok) {
        float acc = 0.f;
        #pragma unroll
        for (int k = 0; k < 64; k++) acc += zs[r * 65 + k] * w2s[k * 16 + tc];
        float di = rsqrtf((float)g_cnt[row] + 1.0f);
        g_y2[(size_t)row * 16 + tc] = di * acc;
    }
}

// ---------------- K7: gather16 + bias + log_softmax (fused) ---------------
// 4 lanes per node; width-4 shuffles for row max / sum
__global__ void __launch_bounds__(256) k_gather16(const float* __restrict__ b2,
                                                  float* __restrict__ out, int n) {
    int t = blockIdx.x * blockDim.x + threadIdx.x;
    int node = t >> 2;
    bool valid = node < n;
    int nc = valid ? node : (n - 1);
    int c = t & 3;
    int off = g_off[nc];
    int cnt = g_cnt[nc];
    int end = off + cnt;
    const float4* y4 = (const float4*)g_y2;
    float4 acc = make_float4(0.f, 0.f, 0.f, 0.f);
    int i = off;
    for (; i + 2 <= end; i += 2) {
        int s0 = g_srcs[i], s1 = g_srcs[i + 1];
        float4 v0 = y4[(size_t)s0 * 4 + c];
        float4 v1 = y4[(size_t)s1 * 4 + c];
        acc.x += v0.x + v1.x; acc.y += v0.y + v1.y;
        acc.z += v0.z + v1.z; acc.w += v0.w + v1.w;
    }
    if (i < end) {
        float4 v0 = y4[(size_t)g_srcs[i] * 4 + c];
        acc.x += v0.x; acc.y += v0.y; acc.z += v0.z; acc.w += v0.w;
    }
    float di = rsqrtf((float)cnt + 1.0f);
    float4 yv = y4[(size_t)nc * 4 + c];
    float4 bv = __ldg(&((const float4*)b2)[c]);
    float4 v;
    v.x = di * (acc.x + yv.x) + bv.x;
    v.y = di * (acc.y + yv.y) + bv.y;
    v.z = di * (acc.z + yv.z) + bv.z;
    v.w = di * (acc.w + yv.w) + bv.w;
    // row max over 16 values (4 per lane × 4 lanes)
    float mx = fmaxf(fmaxf(v.x, v.y), fmaxf(v.z, v.w));
    mx = fmaxf(mx, __shfl_xor_sync(0xffffffffu, mx, 1, 4));
    mx = fmaxf(mx, __shfl_xor_sync(0xffffffffu, mx, 2, 4));
    float s4 = __expf(v.x - mx) + __expf(v.y - mx) + __expf(v.z - mx) + __expf(v.w - mx);
    s4 += __shfl_xor_sync(0xffffffffu, s4, 1, 4);
    s4 += __shfl_xor_sync(0xffffffffu, s4, 2, 4);
    float ls = logf(s4);
    if (valid) {
        float4 o;
        o.x = (v.x - mx) - ls; o.y = (v.y - mx) - ls;
        o.z = (v.z - mx) - ls; o.w = (v.w - mx) - ls;
        ((float4*)out)[(size_t)node * 4 + c] = o;
    }
}

// ---------------- launch ---------------------------------------------------
extern "C" void kernel_launch(void* const* d_in, const int* in_sizes, int n_in,
                              void* d_out, int out_size) {
    const float* x  = (const float*)d_in[0];
    const void*  ei = d_in[1];                    // int32 or int64 — probed
    const float* W1 = (const float*)d_in[2];
    const float* b1 = (const float*)d_in[3];
    const float* W2 = (const float*)d_in[4];
    const float* b2 = (const float*)d_in[5];
    float* out = (float*)d_out;

    int n = in_sizes[0] / 64;       // 100000
    int e = in_sizes[1] / 2;        // 1600000

    k_prep<<<(n + 255) / 256, 256>>>((const int*)ei, n);
    k_edges<<<(e + 255) / 256, 256>>>(ei, e);
    k_scan<<<1, 1024>>>(n);
    k_gemm1<<<(n + 63) / 64, 256>>>(x, W1, n);
    k_fill<<<(e + 255) / 256, 256>>>(e);
    k_gather64<<<(n * 16 + 255) / 256, 256>>>(b1, n);
    k_layer2<<<(n + 15) / 16, 256>>>(W2, n);
    k_gather16<<<(n * 4 + 255) / 256, 256>>>(b2, out, n);
}